// round 3
// baseline (speedup 1.0000x reference)
#include <cuda_runtime.h>
#include <cuda_bf16.h>

#define BB   1024
#define NN   50
#define DIN  128
#define DH   256
#define G4   1024
#define DW   64

// ---------------- persistent device state (static, no runtime alloc) ----------------
__device__ float g_h[2][BB * DH];
__device__ float g_c[BB * DH];
__device__ float g_blend1[BB * NN * DW];   // [row=b*50+n][64]
__device__ float g_Wf[DW * DIN];           // fused W1@W_enc
__device__ float g_bf[DW];                 // fused W1@b_enc
__device__ float g_bias[G4];               // b_ih + b_hh
__device__ float g_W2t[DH * DW];           // W2 transposed [h][w]
__device__ int   g_xrow[BB];               // selected row index into targets (b*50+sel), -1 = zeros
__device__ unsigned long long g_sel[BB];   // selected bitmask (N=50 <= 64)

// Accurate-regardless-of-fastmath tanh (expf-based; abs err ~1e-7)
__device__ __forceinline__ float tanh_acc(float x) {
    return 1.0f - 2.0f / (expf(2.0f * x) + 1.0f);
}
__device__ __forceinline__ float sigm(float x) {
    return 1.0f / (1.0f + expf(-x));
}

// ---------------- init: copy state, fuse bias, transpose W2, reset step state ----------------
__global__ void init_kernel(const float* __restrict__ h0, const float* __restrict__ c0,
                            const float* __restrict__ b_ih, const float* __restrict__ b_hh,
                            const float* __restrict__ W2) {
    int i = blockIdx.x * blockDim.x + threadIdx.x;  // 1024*256 = 262144 threads
    g_h[0][i] = h0[i];
    g_c[i]    = c0[i];
    if (i < DH * DW) {
        int h = i >> 6, w = i & 63;
        g_W2t[i] = W2[w * DH + h];
    }
    if (i < G4) g_bias[i] = b_ih[i] + b_hh[i];
    if (i < BB) { g_xrow[i] = -1; g_sel[i] = 0ull; }
}

// ---------------- fused encoder weight: Wf = W1 @ W_enc, bf = W1 @ b_enc ----------------
__global__ void wf_kernel(const float* __restrict__ W1, const float* __restrict__ Wenc,
                          const float* __restrict__ benc) {
    int w = blockIdx.x;        // 64 blocks
    int i = threadIdx.x;       // 128 threads
    const float* w1 = W1 + w * DH;
    float s = 0.f;
    for (int h = 0; h < DH; h++) s += w1[h] * Wenc[h * DIN + i];
    g_Wf[w * DIN + i] = s;
    __shared__ float red[128];
    float p = 0.f;
    for (int h = i; h < DH; h += 128) p += w1[h] * benc[h];
    red[i] = p;
    __syncthreads();
    for (int o = 64; o; o >>= 1) { if (i < o) red[i] += red[i + o]; __syncthreads(); }
    if (i == 0) g_bf[w] = red[0];
}

// ---------------- blend1 = targets @ Wf^T + bf : [51200,128]x[128,64] ----------------
__global__ __launch_bounds__(128) void blend1_kernel(const float* __restrict__ targets) {
    __shared__ __align__(16) float As[32][68];
    __shared__ __align__(16) float Bs[32][68];
    int t   = threadIdx.x;
    int rb0 = blockIdx.x * 64;
    int c0  = (t & 7) * 8;
    int r0  = (t >> 3) * 4;
    float acc[4][8];
    #pragma unroll
    for (int i = 0; i < 4; i++)
        #pragma unroll
        for (int j = 0; j < 8; j++) acc[i][j] = 0.f;

    float4 pa[4], pb[4];
    // prefetch stage 0
    #pragma unroll
    for (int i = 0; i < 4; i++) {
        int f4 = i * 128 + t; int row = f4 >> 3, kq = f4 & 7;
        pa[i] = *(const float4*)(targets + (size_t)(rb0 + row) * DIN + kq * 4);
        pb[i] = *(const float4*)(g_Wf + (size_t)row * DIN + kq * 4);
    }
    #pragma unroll 1
    for (int kt = 0; kt < 4; kt++) {
        __syncthreads();
        #pragma unroll
        for (int i = 0; i < 4; i++) {
            int f4 = i * 128 + t; int row = f4 >> 3, kq = f4 & 7;
            As[kq * 4 + 0][row] = pa[i].x; As[kq * 4 + 1][row] = pa[i].y;
            As[kq * 4 + 2][row] = pa[i].z; As[kq * 4 + 3][row] = pa[i].w;
            Bs[kq * 4 + 0][row] = pb[i].x; Bs[kq * 4 + 1][row] = pb[i].y;
            Bs[kq * 4 + 2][row] = pb[i].z; Bs[kq * 4 + 3][row] = pb[i].w;
        }
        __syncthreads();
        if (kt < 3) {
            int k0 = (kt + 1) * 32;
            #pragma unroll
            for (int i = 0; i < 4; i++) {
                int f4 = i * 128 + t; int row = f4 >> 3, kq = f4 & 7;
                pa[i] = *(const float4*)(targets + (size_t)(rb0 + row) * DIN + k0 + kq * 4);
                pb[i] = *(const float4*)(g_Wf + (size_t)row * DIN + k0 + kq * 4);
            }
        }
        #pragma unroll
        for (int kk = 0; kk < 32; kk++) {
            float4 av  = *reinterpret_cast<const float4*>(&As[kk][r0]);
            float4 bv0 = *reinterpret_cast<const float4*>(&Bs[kk][c0]);
            float4 bv1 = *reinterpret_cast<const float4*>(&Bs[kk][c0 + 4]);
            float a0 = av.x, a1 = av.y, a2 = av.z, a3 = av.w;
            float b[8] = {bv0.x, bv0.y, bv0.z, bv0.w, bv1.x, bv1.y, bv1.z, bv1.w};
            #pragma unroll
            for (int j = 0; j < 8; j++) {
                acc[0][j] += a0 * b[j]; acc[1][j] += a1 * b[j];
                acc[2][j] += a2 * b[j]; acc[3][j] += a3 * b[j];
            }
        }
    }
    #pragma unroll
    for (int i = 0; i < 4; i++) {
        size_t row = (size_t)(rb0 + r0 + i);
        float4 o0, o1;
        o0.x = acc[i][0] + g_bf[c0 + 0]; o0.y = acc[i][1] + g_bf[c0 + 1];
        o0.z = acc[i][2] + g_bf[c0 + 2]; o0.w = acc[i][3] + g_bf[c0 + 3];
        o1.x = acc[i][4] + g_bf[c0 + 4]; o1.y = acc[i][5] + g_bf[c0 + 5];
        o1.z = acc[i][6] + g_bf[c0 + 6]; o1.w = acc[i][7] + g_bf[c0 + 7];
        *(float4*)(g_blend1 + row * DW + c0)     = o0;
        *(float4*)(g_blend1 + row * DW + c0 + 4) = o1;
    }
}

// ---------------- per-step fused GEMM + LSTM cell ----------------
// gates[b][J] = x[b] @ W_ih[J] + h[b] @ W_hh[J] + bias[J];  K = 384 ([x|h])
// CTA tile: 64 rows x 128 gate-cols; tile col c <-> J = (c&3)*256 + jh0 + (c>>2)
__global__ __launch_bounds__(256) void gates_kernel(const float* __restrict__ targets,
                                                    const float* __restrict__ W_ih,
                                                    const float* __restrict__ W_hh,
                                                    int par) {
    __shared__ __align__(16) float As[32][68];
    __shared__ __align__(16) float Bs[32][132];
    __shared__ int sxr[64];
    const float* h_in  = g_h[par];
    float*       h_out = g_h[par ^ 1];
    int t   = threadIdx.x;
    int bm0 = blockIdx.x * 64;
    int jh0 = blockIdx.y * 32;
    if (t < 64) sxr[t] = g_xrow[bm0 + t];
    __syncthreads();
    int c0 = (t & 15) * 8;
    int r0 = (t >> 4) * 4;
    float acc[4][8];
    #pragma unroll
    for (int i = 0; i < 4; i++)
        #pragma unroll
        for (int j = 0; j < 8; j++) acc[i][j] = 0.f;

    float4 pa[2], pb[4];
    // prefetch stage 0 (k0 = 0 < DIN)
    #pragma unroll
    for (int i = 0; i < 2; i++) {
        int f4 = i * 256 + t; int row = f4 >> 3, kq = f4 & 7;
        int xr = sxr[row];
        pa[i] = (xr >= 0) ? *(const float4*)(targets + (size_t)xr * DIN + kq * 4)
                          : make_float4(0.f, 0.f, 0.f, 0.f);
    }
    #pragma unroll
    for (int i = 0; i < 4; i++) {
        int f4 = i * 256 + t; int c = f4 >> 3, kq = f4 & 7;
        int J = (c & 3) * DH + jh0 + (c >> 2);
        pb[i] = *(const float4*)(W_ih + (size_t)J * DIN + kq * 4);
    }

    #pragma unroll 1
    for (int kt = 0; kt < 12; kt++) {
        __syncthreads();
        #pragma unroll
        for (int i = 0; i < 2; i++) {
            int f4 = i * 256 + t; int row = f4 >> 3, kq = f4 & 7;
            As[kq * 4 + 0][row] = pa[i].x; As[kq * 4 + 1][row] = pa[i].y;
            As[kq * 4 + 2][row] = pa[i].z; As[kq * 4 + 3][row] = pa[i].w;
        }
        #pragma unroll
        for (int i = 0; i < 4; i++) {
            int f4 = i * 256 + t; int c = f4 >> 3, kq = f4 & 7;
            Bs[kq * 4 + 0][c] = pb[i].x; Bs[kq * 4 + 1][c] = pb[i].y;
            Bs[kq * 4 + 2][c] = pb[i].z; Bs[kq * 4 + 3][c] = pb[i].w;
        }
        __syncthreads();
        if (kt < 11) {
            int k0 = (kt + 1) * 32;
            #pragma unroll
            for (int i = 0; i < 2; i++) {
                int f4 = i * 256 + t; int row = f4 >> 3, kq = f4 & 7;
                int k = k0 + kq * 4;
                float4 v;
                if (k < DIN) {
                    int xr = sxr[row];
                    v = (xr >= 0) ? *(const float4*)(targets + (size_t)xr * DIN + k)
                                  : make_float4(0.f, 0.f, 0.f, 0.f);
                } else {
                    v = *(const float4*)(h_in + (size_t)(bm0 + row) * DH + (k - DIN));
                }
                pa[i] = v;
            }
            #pragma unroll
            for (int i = 0; i < 4; i++) {
                int f4 = i * 256 + t; int c = f4 >> 3, kq = f4 & 7;
                int J = (c & 3) * DH + jh0 + (c >> 2);
                int k = k0 + kq * 4;
                pb[i] = (k < DIN) ? *(const float4*)(W_ih + (size_t)J * DIN + k)
                                  : *(const float4*)(W_hh + (size_t)J * DH + (k - DIN));
            }
        }
        #pragma unroll
        for (int kk = 0; kk < 32; kk++) {
            float4 av  = *reinterpret_cast<const float4*>(&As[kk][r0]);
            float4 bv0 = *reinterpret_cast<const float4*>(&Bs[kk][c0]);
            float4 bv1 = *reinterpret_cast<const float4*>(&Bs[kk][c0 + 4]);
            float a0 = av.x, a1 = av.y, a2 = av.z, a3 = av.w;
            float b[8] = {bv0.x, bv0.y, bv0.z, bv0.w, bv1.x, bv1.y, bv1.z, bv1.w};
            #pragma unroll
            for (int j = 0; j < 8; j++) {
                acc[0][j] += a0 * b[j]; acc[1][j] += a1 * b[j];
                acc[2][j] += a2 * b[j]; acc[3][j] += a3 * b[j];
            }
        }
    }

    // LSTM epilogue: each thread's 8 cols = 2 complete (i,f,g,o) quadruples
    int jjb = c0 >> 2;
    #pragma unroll
    for (int i = 0; i < 4; i++) {
        size_t row = (size_t)(bm0 + r0 + i);
        #pragma unroll
        for (int q = 0; q < 2; q++) {
            int hidx = jh0 + jjb + q;
            float ig = acc[i][4 * q + 0] + g_bias[hidx];
            float fg = acc[i][4 * q + 1] + g_bias[DH + hidx];
            float gg = acc[i][4 * q + 2] + g_bias[2 * DH + hidx];
            float og = acc[i][4 * q + 3] + g_bias[3 * DH + hidx];
            float cold = g_c[row * DH + hidx];
            float cn = sigm(fg) * cold + sigm(ig) * tanh_acc(gg);
            g_c[row * DH + hidx]  = cn;
            h_out[row * DH + hidx] = sigm(og) * tanh_acc(cn);
        }
    }
}

// ---------------- per-step attention + argmax + softmax (1 block / batch row) ----------------
__global__ __launch_bounds__(128) void attn_kernel(const float* __restrict__ vt,
                                                   float* __restrict__ out,
                                                   int step, int hpar) {
    int b = blockIdx.x;
    int t = threadIdx.x;
    int lane = t & 31, warp = t >> 5;
    const float* h_in = g_h[hpar];
    __shared__ float sh_h[DH], sh_b2[DW], sh_vt[DW], sh_out[64], sh_red[4], sh_part[128];
    __shared__ float sh_max;
    __shared__ int sh_selidx;

    sh_h[t]       = h_in[(size_t)b * DH + t];
    sh_h[t + 128] = h_in[(size_t)b * DH + 128 + t];
    if (t < DW) sh_vt[t] = vt[t];
    __syncthreads();

    // blend2 = h @ W2^T  (W2t[h][w], coalesced)
    {
        int w = t & 63, half = t >> 6;
        const float* w2p = g_W2t + (size_t)half * 128 * DW + w;
        float s = 0.f;
        #pragma unroll 8
        for (int hh = 0; hh < 128; hh++)
            s += sh_h[half * 128 + hh] * w2p[(size_t)hh * DW];
        sh_part[t] = s;
    }
    __syncthreads();
    if (t < DW) sh_b2[t] = sh_part[t] + sh_part[t + 64];
    __syncthreads();

    unsigned long long selb = g_sel[b];
    const float* b1 = g_blend1 + (size_t)b * NN * DW;

    // out[n] = sum_w tanh(blend1 + blend2) * vt  (warp per n)
    for (int n = warp; n < NN; n += 4) {
        float v = tanh_acc(b1[n * DW + lane]      + sh_b2[lane])      * sh_vt[lane]
                + tanh_acc(b1[n * DW + 32 + lane] + sh_b2[32 + lane]) * sh_vt[32 + lane];
        #pragma unroll
        for (int o = 16; o; o >>= 1) v += __shfl_xor_sync(0xffffffffu, v, o);
        if (lane == 0) sh_out[n] = ((selb >> n) & 1ull) ? -1.0e9f : v;
    }
    __syncthreads();

    // argmax (first index on ties) by warp 0
    if (warp == 0) {
        float v1 = sh_out[lane];
        float v2 = (lane + 32 < NN) ? sh_out[lane + 32] : -3.4e38f;
        float bv; int bi;
        if (v2 > v1) { bv = v2; bi = lane + 32; } else { bv = v1; bi = lane; }
        #pragma unroll
        for (int o = 16; o; o >>= 1) {
            float ov = __shfl_xor_sync(0xffffffffu, bv, o);
            int   oi = __shfl_xor_sync(0xffffffffu, bi, o);
            if (ov > bv || (ov == bv && oi < bi)) { bv = ov; bi = oi; }
        }
        if (lane == 0) { sh_selidx = bi; sh_max = bv; }
    }
    __syncthreads();

    // softmax with 1e-9 floor
    float e = 0.f;
    if (t < NN) e = expf(sh_out[t] - sh_max);
    float s = e;
    #pragma unroll
    for (int o = 16; o; o >>= 1) s += __shfl_xor_sync(0xffffffffu, s, o);
    if (lane == 0) sh_red[warp] = s;
    __syncthreads();
    float total = sh_red[0] + sh_red[1] + sh_red[2] + sh_red[3];
    if (t < NN)
        out[(size_t)b * NN * NN + (size_t)step * NN + t] = fmaxf(e / total, 1e-9f);

    if (t == 0) {
        g_sel[b]  = selb | (1ull << sh_selidx);
        g_xrow[b] = b * NN + sh_selidx;
    }
}

// ---------------- launch ----------------
extern "C" void kernel_launch(void* const* d_in, const int* in_sizes, int n_in,
                              void* d_out, int out_size) {
    const float* targets = (const float*)d_in[0];
    const float* h0      = (const float*)d_in[1];
    const float* c0      = (const float*)d_in[2];
    const float* W_enc   = (const float*)d_in[3];
    const float* b_enc   = (const float*)d_in[4];
    const float* W_ih    = (const float*)d_in[5];
    const float* W_hh    = (const float*)d_in[6];
    const float* b_ih    = (const float*)d_in[7];
    const float* b_hh    = (const float*)d_in[8];
    const float* W1      = (const float*)d_in[9];
    const float* W2      = (const float*)d_in[10];
    const float* vt      = (const float*)d_in[11];
    float* out = (float*)d_out;

    init_kernel<<<1024, 256>>>(h0, c0, b_ih, b_hh, W2);
    wf_kernel<<<64, 128>>>(W1, W_enc, b_enc);
    blend1_kernel<<<BB * NN / 64, 128>>>(targets);

    for (int s = 0; s < NN; s++) {
        int par = s & 1;
        gates_kernel<<<dim3(16, 8), 256>>>(targets, W_ih, W_hh, par);
        attn_kernel<<<BB, 128>>>(vt, out, s, par ^ 1);
    }
}